// round 15
// baseline (speedup 1.0000x reference)
#include <cuda_runtime.h>
#include <cuda_bf16.h>
#include <math.h>
#include <stdint.h>

#define BATCH 4
#define SEQ 8192
#define DMODEL 512
#define NHEADS 8
#define HDIM 64
#define WIN 128
#define CHUNKS 64
#define CSIZE 128
#define LATD 256
#define LHEADS 4
#define LHDIM 64
#define MTOK (BATCH*SEQ)   /* 32768 */

/* ================= scratch (no allocations allowed) ================= */
__device__ float g_rq[MTOK*LATD];
__device__ float g_pooled[BATCH*CHUNKS*DMODEL];
__device__ float g_gk[BATCH*CHUNKS*LATD];
__device__ float g_gv[BATCH*CHUNKS*LATD];
__device__ float g_local[MTOK*DMODEL];
__device__ float g_remote[MTOK*DMODEL];

/* bf16 hi/lo split tensors */
__device__ __nv_bfloat16 g_qh[MTOK*DMODEL], g_ql[MTOK*DMODEL];
__device__ __nv_bfloat16 g_kh[MTOK*DMODEL], g_kl[MTOK*DMODEL];
__device__ __nv_bfloat16 g_vh[MTOK*DMODEL], g_vl[MTOK*DMODEL];
__device__ __nv_bfloat16 g_xh[MTOK*DMODEL],  g_xl[MTOK*DMODEL];
__device__ __nv_bfloat16 g_ph[BATCH*CHUNKS*DMODEL], g_pl[BATCH*CHUNKS*DMODEL];
__device__ __nv_bfloat16 g_lath[MTOK*LATD],  g_latl[MTOK*LATD];
__device__ __nv_bfloat16 g_fush[MTOK*DMODEL], g_fusl[MTOK*DMODEL];

/* transposed bf16 hi/lo weights, stored [N,K] K-major */
__device__ __nv_bfloat16 g_wqt_h[DMODEL*DMODEL],  g_wqt_l[DMODEL*DMODEL];
__device__ __nv_bfloat16 g_wkt_h[DMODEL*DMODEL],  g_wkt_l[DMODEL*DMODEL];
__device__ __nv_bfloat16 g_wvt_h[DMODEL*DMODEL],  g_wvt_l[DMODEL*DMODEL];
__device__ __nv_bfloat16 g_wrqt_h[LATD*DMODEL],   g_wrqt_l[LATD*DMODEL];
__device__ __nv_bfloat16 g_wrkt_h[LATD*DMODEL],   g_wrkt_l[LATD*DMODEL];
__device__ __nv_bfloat16 g_wrvt_h[LATD*DMODEL],   g_wrvt_l[LATD*DMODEL];
__device__ __nv_bfloat16 g_wrot_h[DMODEL*LATD],   g_wrot_l[DMODEL*LATD];
__device__ __nv_bfloat16 g_wot_h[DMODEL*DMODEL],  g_wot_l[DMODEL*DMODEL];

/* ================= PTX helpers (sm_80-class) ================= */

__device__ __forceinline__ uint32_t smem_to_u32(const void* p) {
    uint32_t a;
    asm("{ .reg .u64 t; cvta.to.shared.u64 t, %1; cvt.u32.u64 %0, t; }" : "=r"(a) : "l"(p));
    return a;
}

__device__ __forceinline__ void cp_async16(uint32_t dst, const void* src) {
    asm volatile("cp.async.cg.shared.global [%0], [%1], 16;" :: "r"(dst), "l"(src) : "memory");
}
#define CP_COMMIT() asm volatile("cp.async.commit_group;" ::: "memory")

__device__ __forceinline__ void ldm_x4(uint32_t r[4], uint32_t addr) {
    asm volatile("ldmatrix.sync.aligned.m8n8.x4.shared.b16 {%0,%1,%2,%3}, [%4];"
        : "=r"(r[0]), "=r"(r[1]), "=r"(r[2]), "=r"(r[3]) : "r"(addr));
}

__device__ __forceinline__ void ldm_x4_trans(uint32_t r[4], uint32_t addr) {
    asm volatile("ldmatrix.sync.aligned.m8n8.x4.trans.shared.b16 {%0,%1,%2,%3}, [%4];"
        : "=r"(r[0]), "=r"(r[1]), "=r"(r[2]), "=r"(r[3]) : "r"(addr));
}

__device__ __forceinline__ void mma_bf16(float c[4], const uint32_t a[4], uint32_t b0, uint32_t b1) {
    asm volatile(
        "mma.sync.aligned.m16n8k16.row.col.f32.bf16.bf16.f32 "
        "{%0,%1,%2,%3}, {%4,%5,%6,%7}, {%8,%9}, {%0,%1,%2,%3};"
        : "+f"(c[0]), "+f"(c[1]), "+f"(c[2]), "+f"(c[3])
        : "r"(a[0]), "r"(a[1]), "r"(a[2]), "r"(a[3]), "r"(b0), "r"(b1));
}

__device__ __forceinline__ uint32_t packbf(float x, float y) {
    __nv_bfloat162 t = __floats2bfloat162_rn(x, y);
    return *reinterpret_cast<uint32_t*>(&t);
}

/* ================= conversion kernels ================= */

__global__ void fsplit_kernel(const float* __restrict__ in,
                              __nv_bfloat16* __restrict__ hi,
                              __nv_bfloat16* __restrict__ lo, int n4) {
    int i = blockIdx.x * 256 + threadIdx.x;
    if (i >= n4) return;
    float4 v = reinterpret_cast<const float4*>(in)[i];
    __nv_bfloat16 hx = __float2bfloat16(v.x);
    __nv_bfloat16 hy = __float2bfloat16(v.y);
    __nv_bfloat16 hz = __float2bfloat16(v.z);
    __nv_bfloat16 hw = __float2bfloat16(v.w);
    __nv_bfloat16 lx = __float2bfloat16(v.x - __bfloat162float(hx));
    __nv_bfloat16 ly = __float2bfloat16(v.y - __bfloat162float(hy));
    __nv_bfloat16 lz = __float2bfloat16(v.z - __bfloat162float(hz));
    __nv_bfloat16 lw = __float2bfloat16(v.w - __bfloat162float(hw));
    __nv_bfloat162* H = reinterpret_cast<__nv_bfloat162*>(hi);
    __nv_bfloat162* L = reinterpret_cast<__nv_bfloat162*>(lo);
    H[2*i]   = __nv_bfloat162(hx, hy);
    H[2*i+1] = __nv_bfloat162(hz, hw);
    L[2*i]   = __nv_bfloat162(lx, ly);
    L[2*i+1] = __nv_bfloat162(lz, lw);
}

/* W[K,N] fp32 -> Wt hi/lo [N,K] bf16 (transpose + split) */
__global__ void wsplit_kernel(const float* __restrict__ W,
                              __nv_bfloat16* __restrict__ th,
                              __nv_bfloat16* __restrict__ tl, int K, int N) {
    __shared__ float t[32][33];
    int n0 = blockIdx.x * 32, k0 = blockIdx.y * 32;
    for (int r = threadIdx.y; r < 32; r += 8)
        t[r][threadIdx.x] = W[(size_t)(k0 + r) * N + n0 + threadIdx.x];
    __syncthreads();
    for (int r = threadIdx.y; r < 32; r += 8) {
        float v = t[threadIdx.x][r];
        __nv_bfloat16 h = __float2bfloat16(v);
        __nv_bfloat16 l = __float2bfloat16(v - __bfloat162float(h));
        size_t o = (size_t)(n0 + r) * K + k0 + threadIdx.x;
        th[o] = h;
        tl[o] = l;
    }
}

/* ================= bf16x3 tensor-core GEMM (mma.sync, 2 CTAs/SM) ================= */

#define TSTRIDE 40
#define TILE_BYTES (128*TSTRIDE*2)
#define STAGE_BYTES (4*TILE_BYTES)
#define GEMM_SMEM (2*STAGE_BYTES)

#define OFF_AH 0
#define OFF_AL (TILE_BYTES)
#define OFF_BH (2*TILE_BYTES)
#define OFF_BL (3*TILE_BYTES)

__global__ void __launch_bounds__(256, 2)
gemm_tc_kernel(const __nv_bfloat16* __restrict__ Ah, const __nv_bfloat16* __restrict__ Al,
               const __nv_bfloat16* __restrict__ Bh, const __nv_bfloat16* __restrict__ Bl,
               const float* __restrict__ bias, float* __restrict__ C,
               __nv_bfloat16* __restrict__ Ch, __nv_bfloat16* __restrict__ Cl,
               int K, int Ntot, int nch) {
    extern __shared__ char smem[];
    const uint32_t sbase = smem_to_u32(smem);
    const int tid = threadIdx.x;
    const int wid = tid >> 5, lane = tid & 31;
    const int wr = wid & 3, wc = wid >> 2;
    const int m0 = blockIdx.y * 128, n0 = blockIdx.x * 128;

    float acc[2][8][4];
#pragma unroll
    for (int i = 0; i < 2; i++)
#pragma unroll
        for (int j = 0; j < 8; j++)
#pragma unroll
            for (int e = 0; e < 4; e++) acc[i][j][e] = 0.f;

    const int lrow[2] = { tid >> 2, (tid + 256) >> 2 };
    const int lcol = (tid & 3) * 8;

    auto load_stage = [&](int s, int c) {
        uint32_t sb = sbase + s * STAGE_BYTES;
        const int kof = c * 32 + lcol;
#pragma unroll
        for (int it = 0; it < 2; it++) {
            int r = lrow[it];
            uint32_t so = (r * TSTRIDE + lcol) * 2;
            cp_async16(sb + OFF_AH + so, Ah + (size_t)(m0 + r) * K + kof);
            cp_async16(sb + OFF_AL + so, Al + (size_t)(m0 + r) * K + kof);
            cp_async16(sb + OFF_BH + so, Bh + (size_t)(n0 + r) * K + kof);
            cp_async16(sb + OFF_BL + so, Bl + (size_t)(n0 + r) * K + kof);
        }
        CP_COMMIT();
    };

    load_stage(0, 0);

    const int a_row = wr * 32 + (lane & 15);
    const int a_kof = (lane >> 4) * 8;
    const int qd = lane >> 3;
    const int b_row = wc * 64 + ((qd & 2) << 2) + (lane & 7);
    const int b_kof = (qd & 1) * 8;

    for (int c = 0; c < nch; c++) {
        const int s = c & 1;
        if (c + 1 < nch) load_stage(s ^ 1, c + 1);
        if (c + 1 < nch) asm volatile("cp.async.wait_group 1;" ::: "memory");
        else             asm volatile("cp.async.wait_group 0;" ::: "memory");
        __syncthreads();

        const uint32_t sb = sbase + s * STAGE_BYTES;
#pragma unroll
        for (int ks = 0; ks < 2; ks++) {
            const int k0 = ks * 16;
            uint32_t ah[2][4], al[2][4];
#pragma unroll
            for (int i = 0; i < 2; i++) {
                uint32_t ao = ((a_row + i * 16) * TSTRIDE + k0 + a_kof) * 2;
                ldm_x4(ah[i], sb + OFF_AH + ao);
                ldm_x4(al[i], sb + OFF_AL + ao);
            }
#pragma unroll
            for (int j2 = 0; j2 < 4; j2++) {
                uint32_t bo = ((b_row + j2 * 16) * TSTRIDE + k0 + b_kof) * 2;
                uint32_t bh[4], bl[4];
                ldm_x4(bh, sb + OFF_BH + bo);
                ldm_x4(bl, sb + OFF_BL + bo);
#pragma unroll
                for (int i = 0; i < 2; i++)
#pragma unroll
                    for (int jj = 0; jj < 2; jj++) {
                        int j = j2 * 2 + jj;
                        mma_bf16(acc[i][j], ah[i], bh[jj * 2], bh[jj * 2 + 1]);
                        mma_bf16(acc[i][j], ah[i], bl[jj * 2], bl[jj * 2 + 1]);
                        mma_bf16(acc[i][j], al[i], bh[jj * 2], bh[jj * 2 + 1]);
                    }
            }
        }
        __syncthreads();
    }

    const int erow = m0 + wr * 32 + (lane >> 2);
    const int ecol0 = n0 + wc * 64 + (lane & 3) * 2;
#pragma unroll
    for (int i = 0; i < 2; i++) {
#pragma unroll
        for (int j = 0; j < 8; j++) {
            int col = ecol0 + j * 8;
            float2 b2 = *reinterpret_cast<const float2*>(bias + col);
            float v0 = acc[i][j][0] + b2.x, v1 = acc[i][j][1] + b2.y;
            float v2 = acc[i][j][2] + b2.x, v3 = acc[i][j][3] + b2.y;
            size_t o0 = (size_t)(erow + i * 16) * Ntot + col;
            size_t o1 = (size_t)(erow + i * 16 + 8) * Ntot + col;
            if (C) {
                *reinterpret_cast<float2*>(C + o0) = make_float2(v0, v1);
                *reinterpret_cast<float2*>(C + o1) = make_float2(v2, v3);
            } else {
                __nv_bfloat16 h0 = __float2bfloat16(v0), h1 = __float2bfloat16(v1);
                __nv_bfloat16 h2 = __float2bfloat16(v2), h3 = __float2bfloat16(v3);
                *reinterpret_cast<__nv_bfloat162*>(Ch + o0) = __nv_bfloat162(h0, h1);
                *reinterpret_cast<__nv_bfloat162*>(Ch + o1) = __nv_bfloat162(h2, h3);
                *reinterpret_cast<__nv_bfloat162*>(Cl + o0) = __nv_bfloat162(
                    __float2bfloat16(v0 - __bfloat162float(h0)),
                    __float2bfloat16(v1 - __bfloat162float(h1)));
                *reinterpret_cast<__nv_bfloat162*>(Cl + o1) = __nv_bfloat162(
                    __float2bfloat16(v2 - __bfloat162float(h2)),
                    __float2bfloat16(v3 - __bfloat162float(h3)));
            }
        }
    }
}

/* ================= pooling ================= */
__global__ void pool_kernel(const float* __restrict__ x, float* __restrict__ pooled) {
    int bc = blockIdx.x;
    int b = bc / CHUNKS, c = bc % CHUNKS;
    int d = threadIdx.x;
    const float* base = x + ((size_t)b * SEQ + (size_t)c * CSIZE) * DMODEL + d;
    float s = 0.f;
    for (int t = 0; t < CSIZE; t++) s += base[(size_t)t * DMODEL];
    pooled[(size_t)bc * DMODEL + d] = s * (1.0f / CSIZE);
}

/* ================= FA2-style tensor-core sliding-window attention ================= */

#define ATT_STRIDE 72
#define ATT_TILE (128*ATT_STRIDE)
#define ATT_SMEM (6 * ATT_TILE * 2)   /* 110592 */

__global__ void __launch_bounds__(256, 2)
local_attn_tc_kernel(const __nv_bfloat16* __restrict__ Qh, const __nv_bfloat16* __restrict__ Ql,
                     const __nv_bfloat16* __restrict__ Kh, const __nv_bfloat16* __restrict__ Kl,
                     const __nv_bfloat16* __restrict__ Vh, const __nv_bfloat16* __restrict__ Vl,
                     float* __restrict__ out) {
    extern __shared__ __nv_bfloat16 smm[];
    const uint32_t sbase = smem_to_u32(smm);
    const int qb = blockIdx.x, h = blockIdx.y, b = blockIdx.z;
    const int qstart = qb * 128;
    const int tid = threadIdx.x, wid = tid >> 5, lane = tid & 31;

    const uint32_t sQh = sbase,                 sQl = sbase + ATT_TILE * 2;
    const uint32_t sKh_ = sbase + 2 * ATT_TILE * 2, sKl_ = sbase + 3 * ATT_TILE * 2;
    const uint32_t sVh_ = sbase + 4 * ATT_TILE * 2, sVl_ = sbase + 5 * ATT_TILE * 2;
    const size_t base_tok = (size_t)b * SEQ;

    auto load_q = [&]() {
#pragma unroll
        for (int it = 0; it < 4; it++) {
            int idx = tid + it * 256;
            int r = idx >> 3, c = (idx & 7) * 8;
            size_t go = (base_tok + qstart + r) * DMODEL + h * HDIM + c;
            uint32_t so = (r * ATT_STRIDE + c) * 2;
            cp_async16(sQh + so, Qh + go);
            cp_async16(sQl + so, Ql + go);
        }
    };
    auto load_kv = [&](int kstart) {
#pragma unroll
        for (int it = 0; it < 4; it++) {
            int idx = tid + it * 256;
            int r = idx >> 3, c = (idx & 7) * 8;
            size_t go = (base_tok + kstart + r) * DMODEL + h * HDIM + c;
            uint32_t so = (r * ATT_STRIDE + c) * 2;
            cp_async16(sKh_ + so, Kh + go);
            cp_async16(sKl_ + so, Kl + go);
            cp_async16(sVh_ + so, Vh + go);
            cp_async16(sVl_ + so, Vl + go);
        }
    };

    const int tfirst = (qb > 0) ? 0 : 1;
    load_q();
    load_kv(tfirst == 0 ? qstart - 128 : qstart);
    CP_COMMIT();
    asm volatile("cp.async.wait_group 0;" ::: "memory");
    __syncthreads();

    uint32_t ah[4][4], al[4][4];
    {
        int ar = wid * 16 + (lane & 15);
        int ac = (lane >> 4) * 8;
#pragma unroll
        for (int kc = 0; kc < 4; kc++) {
            uint32_t ao = (ar * ATT_STRIDE + kc * 16 + ac) * 2;
            ldm_x4(ah[kc], sQh + ao);
            ldm_x4(al[kc], sQl + ao);
        }
    }

    float m0 = -1e30f, m1 = -1e30f, l0 = 0.f, l1 = 0.f;
    float acc[8][4];
#pragma unroll
    for (int j = 0; j < 8; j++)
#pragma unroll
        for (int e = 0; e < 4; e++) acc[j][e] = 0.f;

    const int rloc = wid * 16 + (lane >> 2);
    const int qd2 = lane >> 3;
    const int brow = ((qd2 & 2) << 2) + (lane & 7);
    const int bkof = (qd2 & 1) * 8;
    const int vrow = (lane & 7) + ((lane >> 3) & 1) * 8;
    const int vcol = (lane >> 4) * 8;

    auto process_tile = [&](int t) {
        const int koff = (t == 0) ? 128 : 0;
#pragma unroll
        for (int hn = 0; hn < 2; hn++) {
            if (t == 0 ? (hn * 4 + 3 < wid) : (hn * 4 > wid)) continue;

            float sc[8][4];
#pragma unroll
            for (int j = 0; j < 8; j++)
#pragma unroll
                for (int e = 0; e < 4; e++) sc[j][e] = 0.f;

#pragma unroll
            for (int j2l = 0; j2l < 4; j2l++) {
                int j2g = hn * 4 + j2l;
                if (t == 0 ? (j2g < wid) : (j2g > wid)) continue;
#pragma unroll
                for (int kc = 0; kc < 4; kc++) {
                    uint32_t bo = ((j2g * 16 + brow) * ATT_STRIDE + kc * 16 + bkof) * 2;
                    uint32_t bh[4], bl[4];
                    ldm_x4(bh, sKh_ + bo);
                    ldm_x4(bl, sKl_ + bo);
                    mma_bf16(sc[2 * j2l],     ah[kc], bh[0], bh[1]);
                    mma_bf16(sc[2 * j2l + 1], ah[kc], bh[2], bh[3]);
                    mma_bf16(sc[2 * j2l],     ah[kc], bl[0], bl[1]);
                    mma_bf16(sc[2 * j2l + 1], ah[kc], bl[2], bl[3]);
                    mma_bf16(sc[2 * j2l],     al[kc], bh[0], bh[1]);
                    mma_bf16(sc[2 * j2l + 1], al[kc], bh[2], bh[3]);
                }
            }

#pragma unroll
            for (int j = 0; j < 8; j++) {
                int ck = hn * 64 + j * 8 + (lane & 3) * 2;
#pragma unroll
                for (int e = 0; e < 4; e++) {
                    int r = rloc + ((e >> 1) << 3);
                    int d = r - (ck + (e & 1)) + koff;
                    sc[j][e] = (d >= 0 && d < WIN) ? sc[j][e] * 0.125f : -INFINITY;
                }
            }

            float mx0 = -INFINITY, mx1 = -INFINITY;
#pragma unroll
            for (int j = 0; j < 8; j++) {
                mx0 = fmaxf(mx0, fmaxf(sc[j][0], sc[j][1]));
                mx1 = fmaxf(mx1, fmaxf(sc[j][2], sc[j][3]));
            }
            mx0 = fmaxf(mx0, __shfl_xor_sync(0xffffffffu, mx0, 1));
            mx0 = fmaxf(mx0, __shfl_xor_sync(0xffffffffu, mx0, 2));
            mx1 = fmaxf(mx1, __shfl_xor_sync(0xffffffffu, mx1, 1));
            mx1 = fmaxf(mx1, __shfl_xor_sync(0xffffffffu, mx1, 2));
            float mn0 = fmaxf(fmaxf(m0, mx0), -1e30f);
            float mn1 = fmaxf(fmaxf(m1, mx1), -1e30f);
            float s0 = __expf(m0 - mn0), s1 = __expf(m1 - mn1);
            m0 = mn0; m1 = mn1;
            float rs0 = 0.f, rs1 = 0.f;
#pragma unroll
            for (int j = 0; j < 8; j++) {
                sc[j][0] = __expf(sc[j][0] - mn0);
                sc[j][1] = __expf(sc[j][1] - mn0);
                sc[j][2] = __expf(sc[j][2] - mn1);
                sc[j][3] = __expf(sc[j][3] - mn1);
                rs0 += sc[j][0] + sc[j][1];
                rs1 += sc[j][2] + sc[j][3];
            }
            rs0 += __shfl_xor_sync(0xffffffffu, rs0, 1);
            rs0 += __shfl_xor_sync(0xffffffffu, rs0, 2);
            rs1 += __shfl_xor_sync(0xffffffffu, rs1, 1);
            rs1 += __shfl_xor_sync(0xffffffffu, rs1, 2);
            l0 = l0 * s0 + rs0;
            l1 = l1 * s1 + rs1;
#pragma unroll
            for (int j = 0; j < 8; j++) {
                acc[j][0] *= s0; acc[j][1] *= s0;
                acc[j][2] *= s1; acc[j][3] *= s1;
            }

#pragma unroll
            for (int kcl = 0; kcl < 4; kcl++) {
                int kcg = hn * 4 + kcl;
                if (t == 0 ? (kcg < wid) : (kcg > wid)) continue;
                uint32_t pah[4], pal[4];
#pragma unroll
                for (int half = 0; half < 2; half++) {
                    int j = 2 * kcl + half;
                    float p0 = sc[j][0], p1 = sc[j][1], p2 = sc[j][2], p3 = sc[j][3];
                    float h0 = __bfloat162float(__float2bfloat16(p0));
                    float h1 = __bfloat162float(__float2bfloat16(p1));
                    float h2 = __bfloat162float(__float2bfloat16(p2));
                    float h3 = __bfloat162float(__float2bfloat16(p3));
                    pah[half * 2]     = packbf(h0, h1);
                    pah[half * 2 + 1] = packbf(h2, h3);
                    pal[half * 2]     = packbf(p0 - h0, p1 - h1);
                    pal[half * 2 + 1] = packbf(p2 - h2, p3 - h3);
                }
#pragma unroll
                for (int jn = 0; jn < 4; jn++) {
                    uint32_t vo = ((kcg * 16 + vrow) * ATT_STRIDE + jn * 16 + vcol) * 2;
                    uint32_t vbh[4], vbl[4];
                    ldm_x4_trans(vbh, sVh_ + vo);
                    ldm_x4_trans(vbl, sVl_ + vo);
                    mma_bf16(acc[2 * jn],     pah, vbh[0], vbh[1]);
                    mma_bf16(acc[2 * jn + 1], pah, vbh[2], vbh[3]);
                    mma_bf16(acc[2 * jn],     pah, vbl[0], vbl[1]);
                    mma_bf16(acc[2 * jn + 1], pah, vbl[2], vbl[3]);
                    mma_bf16(acc[2 * jn],     pal, vbh[0], vbh[1]);
                    mma_bf16(acc[2 * jn + 1], pal, vbh[2], vbh[3]);
                }
            }
        }
    };

    process_tile(tfirst);
    if (tfirst == 0) {
        __syncthreads();
        load_kv(qstart);
        CP_COMMIT();
        asm volatile("cp.async.wait_group 0;" ::: "memory");
        __syncthreads();
        process_tile(1);
    }

    float i0 = 1.f / l0, i1 = 1.f / l1;
    size_t ob = (base_tok + qstart + rloc) * DMODEL + h * HDIM;
#pragma unroll
    for (int j = 0; j < 8; j++) {
        int col = j * 8 + (lane & 3) * 2;
        *reinterpret_cast<float2*>(out + ob + col) =
            make_float2(acc[j][0] * i0, acc[j][1] * i0);
        *reinterpret_cast<float2*>(out + ob + (size_t)8 * DMODEL + col) =
            make_float2(acc[j][2] * i1, acc[j][3] * i1);
    }
}

/* ================= latent attention (score-cached, bf16 h/l epilogue) ============== */
#define LATENT_SMEM ((2*CHUNKS*LHDIM + 128*65) * (int)sizeof(float))

__global__ void __launch_bounds__(128, 1)
latent_attn_kernel(const float* __restrict__ rq,
                   const float* __restrict__ gk,
                   const float* __restrict__ gv,
                   __nv_bfloat16* __restrict__ lath,
                   __nv_bfloat16* __restrict__ latl) {
    extern __shared__ float sm[];
    float* Ks = sm;
    float* Vs = sm + CHUNKS * LHDIM;
    float* Sc = sm + 2 * CHUNKS * LHDIM;
    const int cid = blockIdx.x;
    const int lh = blockIdx.y, b = blockIdx.z;
    const int tid = threadIdx.x;

    const int pos = cid * 128 + tid;
    const size_t qoff = ((size_t)b * SEQ + pos) * LATD + lh * LHDIM;
    if (cid == 0) {
        __nv_bfloat16 z = __float2bfloat16(0.f);
#pragma unroll
        for (int d = 0; d < 64; d++) { lath[qoff + d] = z; latl[qoff + d] = z; }
        return;
    }
    for (int idx = tid; idx < CHUNKS * LHDIM; idx += 128) {
        int c = idx >> 6, d = idx & 63;
        size_t off = ((size_t)b * CHUNKS + c) * LATD + lh * LHDIM + d;
        Ks[idx] = gk[off];
        Vs[idx] = gv[off];
    }
    __syncthreads();

    float qr[64];
#pragma unroll
    for (int d = 0; d < 64; d++) qr[d] = rq[qoff + d] * 0.125f;

    float* myS = Sc + tid * 65;
    float m = -1e30f;
    for (int c = 0; c < cid; c++) {
        const float* kr = Ks + c * 64;
        float s = 0.f;
#pragma unroll
        for (int d = 0; d < 64; d++) s += qr[d] * kr[d];
        myS[c] = s;
        m = fmaxf(m, s);
    }
    float l = 0.f;
    float acc[64];
#pragma unroll
    for (int d = 0; d < 64; d++) acc[d] = 0.f;
    for (int c = 0; c < cid; c++) {
        float p = __expf(myS[c] - m);
        l += p;
        const float* vr = Vs + c * 64;
#pragma unroll
        for (int d = 0; d < 64; d++) acc[d] += p * vr[d];
    }
    float inv = 1.f / l;
#pragma unroll
    for (int d = 0; d < 64; d++) {
        float val = acc[d] * inv;
        __nv_bfloat16 hh = __float2bfloat16(val);
        lath[qoff + d] = hh;
        latl[qoff + d] = __float2bfloat16(val - __bfloat162float(hh));
    }
}

/* ================= gate fuse (writes bf16 h/l directly) ================= */
__global__ void gate_fuse_kernel(const float* __restrict__ x,
                                 const float* __restrict__ loc,
                                 const float* __restrict__ rem,
                                 const float* __restrict__ Wg,
                                 const float* __restrict__ bg,
                                 __nv_bfloat16* __restrict__ fush,
                                 __nv_bfloat16* __restrict__ fusl) {
    const int tkn = blockIdx.x;
    const int tid = threadIdx.x;
    __shared__ float red[128];
    const float* xr = x + (size_t)tkn * DMODEL;
    const float* lr = loc + (size_t)tkn * DMODEL;
    const float* rr = rem + (size_t)tkn * DMODEL;
    float s = 0.f;
    for (int d = tid; d < DMODEL; d += 128) s += xr[d] * Wg[d] + lr[d] * Wg[DMODEL + d];
    red[tid] = s;
    __syncthreads();
    for (int off = 64; off > 0; off >>= 1) {
        if (tid < off) red[tid] += red[tid + off];
        __syncthreads();
    }
    float g = 1.f / (1.f + __expf(-(red[0] + bg[0])));
    for (int d = tid; d < DMODEL; d += 128) {
        float val = g * lr[d] + (1.f - g) * rr[d];
        __nv_bfloat16 hh = __float2bfloat16(val);
        fush[(size_t)tkn * DMODEL + d] = hh;
        fusl[(size_t)tkn * DMODEL + d] = __float2bfloat16(val - __bfloat162float(hh));
    }
}

/* ================= host ================= */

extern "C" void kernel_launch(void* const* d_in, const int* in_sizes, int n_in,
                              void* d_out, int out_size) {
    const float* x   = (const float*)d_in[0];
    const float* Wq  = (const float*)d_in[1];  const float* bq  = (const float*)d_in[2];
    const float* Wk  = (const float*)d_in[3];  const float* bk  = (const float*)d_in[4];
    const float* Wv  = (const float*)d_in[5];  const float* bv  = (const float*)d_in[6];
    const float* Wrq = (const float*)d_in[7];  const float* brq = (const float*)d_in[8];
    const float* Wrk = (const float*)d_in[9];  const float* brk = (const float*)d_in[10];
    const float* Wrv = (const float*)d_in[11]; const float* brv = (const float*)d_in[12];
    const float* Wro = (const float*)d_in[13]; const float* bro = (const float*)d_in[14];
    const float* Wo  = (const float*)d_in[15]; const float* bo  = (const float*)d_in[16];
    const float* Wg  = (const float*)d_in[17]; const float* bg  = (const float*)d_in[18];
    float* out = (float*)d_out;

    float *rq, *pooled, *gk, *gv, *loc, *rem;
    cudaGetSymbolAddress((void**)&rq, g_rq);
    cudaGetSymbolAddress((void**)&pooled, g_pooled);
    cudaGetSymbolAddress((void**)&gk, g_gk);
    cudaGetSymbolAddress((void**)&gv, g_gv);
    cudaGetSymbolAddress((void**)&loc, g_local);
    cudaGetSymbolAddress((void**)&rem, g_remote);

    __nv_bfloat16 *qh,*ql,*kh,*kl,*vh,*vl;
    cudaGetSymbolAddress((void**)&qh, g_qh); cudaGetSymbolAddress((void**)&ql, g_ql);
    cudaGetSymbolAddress((void**)&kh, g_kh); cudaGetSymbolAddress((void**)&kl, g_kl);
    cudaGetSymbolAddress((void**)&vh, g_vh); cudaGetSymbolAddress((void**)&vl, g_vl);

    __nv_bfloat16 *xh, *xl, *ph, *pl, *lath, *latl, *fush, *fusl;
    cudaGetSymbolAddress((void**)&xh, g_xh);     cudaGetSymbolAddress((void**)&xl, g_xl);
    cudaGetSymbolAddress((void**)&ph, g_ph);     cudaGetSymbolAddress((void**)&pl, g_pl);
    cudaGetSymbolAddress((void**)&lath, g_lath); cudaGetSymbolAddress((void**)&latl, g_latl);
    cudaGetSymbolAddress((void**)&fush, g_fush); cudaGetSymbolAddress((void**)&fusl, g_fusl);

    __nv_bfloat16 *wqh,*wql,*wkh,*wkl,*wvh,*wvl,*wrqh,*wrql,*wrkh,*wrkl,*wrvh,*wrvl,*wroh,*wrol,*woh,*wol;
    cudaGetSymbolAddress((void**)&wqh, g_wqt_h);   cudaGetSymbolAddress((void**)&wql, g_wqt_l);
    cudaGetSymbolAddress((void**)&wkh, g_wkt_h);   cudaGetSymbolAddress((void**)&wkl, g_wkt_l);
    cudaGetSymbolAddress((void**)&wvh, g_wvt_h);   cudaGetSymbolAddress((void**)&wvl, g_wvt_l);
    cudaGetSymbolAddress((void**)&wrqh, g_wrqt_h); cudaGetSymbolAddress((void**)&wrql, g_wrqt_l);
    cudaGetSymbolAddress((void**)&wrkh, g_wrkt_h); cudaGetSymbolAddress((void**)&wrkl, g_wrkt_l);
    cudaGetSymbolAddress((void**)&wrvh, g_wrvt_h); cudaGetSymbolAddress((void**)&wrvl, g_wrvt_l);
    cudaGetSymbolAddress((void**)&wroh, g_wrot_h); cudaGetSymbolAddress((void**)&wrol, g_wrot_l);
    cudaGetSymbolAddress((void**)&woh, g_wot_h);   cudaGetSymbolAddress((void**)&wol, g_wot_l);

    cudaFuncSetAttribute(gemm_tc_kernel,       cudaFuncAttributeMaxDynamicSharedMemorySize, GEMM_SMEM);
    cudaFuncSetAttribute(local_attn_tc_kernel, cudaFuncAttributeMaxDynamicSharedMemorySize, ATT_SMEM);
    cudaFuncSetAttribute(latent_attn_kernel,   cudaFuncAttributeMaxDynamicSharedMemorySize, LATENT_SMEM);

    /* two-stream fork/join */
    static cudaStream_t s2 = nullptr;
    static cudaEvent_t evStart, evX, evWq, evWk, evV, evRem;
    if (!s2) {
        cudaStreamCreateWithFlags(&s2, cudaStreamNonBlocking);
        cudaEventCreateWithFlags(&evStart, cudaEventDisableTiming);
        cudaEventCreateWithFlags(&evX,   cudaEventDisableTiming);
        cudaEventCreateWithFlags(&evWq,  cudaEventDisableTiming);
        cudaEventCreateWithFlags(&evWk,  cudaEventDisableTiming);
        cudaEventCreateWithFlags(&evV,   cudaEventDisableTiming);
        cudaEventCreateWithFlags(&evRem, cudaEventDisableTiming);
    }
    cudaStream_t s0 = 0;

    cudaEventRecord(evStart, s0);
    cudaStreamWaitEvent(s2, evStart, 0);

    /* k0: x split (s0) */
    fsplit_kernel<<<MTOK*DMODEL/4/256, 256, 0, s0>>>(x, xh, xl, MTOK*DMODEL/4);
    cudaEventRecord(evX, s0);

    /* k1-2: Wq, Wk splits (s2) */
    wsplit_kernel<<<dim3(DMODEL/32, DMODEL/32), dim3(32,8), 0, s2>>>(Wq, wqh, wql, DMODEL, DMODEL);
    cudaEventRecord(evWq, s2);
    wsplit_kernel<<<dim3(DMODEL/32, DMODEL/32), dim3(32,8), 0, s2>>>(Wk, wkh, wkl, DMODEL, DMODEL);
    cudaEventRecord(evWk, s2);

    /* k3: q GEMM (s0) — profiled slot */
    cudaStreamWaitEvent(s0, evWq, 0);
    gemm_tc_kernel<<<dim3(4, 256), 256, GEMM_SMEM, s0>>>(xh, xl, wqh, wql, bq, nullptr, qh, ql, DMODEL, DMODEL, 16);

    /* v GEMM on s2: weight split + GEMM (concurrent with k GEMM on s0) */
    wsplit_kernel<<<dim3(DMODEL/32, DMODEL/32), dim3(32,8), 0, s2>>>(Wv, wvh, wvl, DMODEL, DMODEL);
    cudaStreamWaitEvent(s2, evX, 0);
    gemm_tc_kernel<<<dim3(4, 256), 256, GEMM_SMEM, s2>>>(xh, xl, wvh, wvl, bv, nullptr, vh, vl, DMODEL, DMODEL, 16);
    cudaEventRecord(evV, s2);

    /* k GEMM (s0) */
    cudaStreamWaitEvent(s0, evWk, 0);
    gemm_tc_kernel<<<dim3(4, 256), 256, GEMM_SMEM, s0>>>(xh, xl, wkh, wkl, bk, nullptr, kh, kl, DMODEL, DMODEL, 16);

    /* rq projection on s2 (only feeds the latent chain) */
    wsplit_kernel<<<dim3(LATD/32, DMODEL/32), dim3(32,8), 0, s2>>>(Wrq, wrqh, wrql, DMODEL, LATD);
    gemm_tc_kernel<<<dim3(2, 256), 256, GEMM_SMEM, s2>>>(xh, xl, wrqh, wrql, brq, rq, nullptr, nullptr, DMODEL, LATD, 16);

    /* remaining weight prep + latent chain (s2) */
    wsplit_kernel<<<dim3(LATD/32, DMODEL/32), dim3(32,8), 0, s2>>>(Wrk, wrkh, wrkl, DMODEL, LATD);
    wsplit_kernel<<<dim3(LATD/32, DMODEL/32), dim3(32,8), 0, s2>>>(Wrv, wrvh, wrvl, DMODEL, LATD);
    wsplit_kernel<<<dim3(DMODEL/32, LATD/32), dim3(32,8), 0, s2>>>(Wro, wroh, wrol, LATD, DMODEL);
    wsplit_kernel<<<dim3(DMODEL/32, DMODEL/32), dim3(32,8), 0, s2>>>(Wo, woh, wol, DMODEL, DMODEL);
    pool_kernel<<<BATCH*CHUNKS, DMODEL, 0, s2>>>(x, pooled);
    fsplit_kernel<<<BATCH*CHUNKS*DMODEL/4/256, 256, 0, s2>>>(pooled, ph, pl, BATCH*CHUNKS*DMODEL/4);
    gemm_tc_kernel<<<dim3(2, 2), 256, GEMM_SMEM, s2>>>(ph, pl, wrkh, wrkl, brk, gk, nullptr, nullptr, DMODEL, LATD, 16);
    gemm_tc_kernel<<<dim3(2, 2), 256, GEMM_SMEM, s2>>>(ph, pl, wrvh, wrvl, brv, gv, nullptr, nullptr, DMODEL, LATD, 16);
    latent_attn_kernel<<<dim3(SEQ/128, LHEADS, BATCH), 128, LATENT_SMEM, s2>>>(rq, gk, gv, lath, latl);
    gemm_tc_kernel<<<dim3(4, 256), 256, GEMM_SMEM, s2>>>(lath, latl, wroh, wrol, bro, rem, nullptr, nullptr, LATD, DMODEL, 8);
    cudaEventRecord(evRem, s2);

    /* local attention (s0): needs q (in-stream), k (in-stream), v (evV from s2) */
    cudaStreamWaitEvent(s0, evV, 0);
    local_attn_tc_kernel<<<dim3(SEQ/128, NHEADS, BATCH), 256, ATT_SMEM, s0>>>(qh, ql, kh, kl, vh, vl, loc);

    /* join: gate + final projection (s0) */
    cudaStreamWaitEvent(s0, evRem, 0);
    gate_fuse_kernel<<<MTOK, 128, 0, s0>>>(x, loc, rem, Wg, bg, fush, fusl);
    gemm_tc_kernel<<<dim3(4, 256), 256, GEMM_SMEM, s0>>>(fush, fusl, woh, wol, bo, out, nullptr, nullptr, DMODEL, DMODEL, 16);
}

// round 17
// speedup vs baseline: 1.9058x; 1.9058x over previous
#include <cuda_runtime.h>
#include <cuda_fp16.h>
#include <math.h>
#include <stdint.h>

#define BATCH 4
#define SEQ 8192
#define DMODEL 512
#define NHEADS 8
#define HDIM 64
#define WIN 128
#define CHUNKS 64
#define CSIZE 128
#define LATD 256
#define LHEADS 4
#define LHDIM 64
#define MTOK (BATCH*SEQ)   /* 32768 */

/* ================= scratch (no allocations allowed) ================= */
__device__ float g_rq[MTOK*LATD];
__device__ float g_pooled[BATCH*CHUNKS*DMODEL];
__device__ float g_gk[BATCH*CHUNKS*LATD];
__device__ float g_gv[BATCH*CHUNKS*LATD];
__device__ float g_local[MTOK*DMODEL];
__device__ float g_remote[MTOK*DMODEL];

/* fp16 tensors */
__device__ __half g_q16[MTOK*DMODEL];
__device__ __half g_k16[MTOK*DMODEL];
__device__ __half g_v16[MTOK*DMODEL];
__device__ __half g_x16[MTOK*DMODEL];
__device__ __half g_p16[BATCH*CHUNKS*DMODEL];
__device__ __half g_lat16[MTOK*LATD];
__device__ __half g_fus16[MTOK*DMODEL];

/* transposed fp16 weights, stored [N,K] K-major */
__device__ __half g_wqt[DMODEL*DMODEL];
__device__ __half g_wkt[DMODEL*DMODEL];
__device__ __half g_wvt[DMODEL*DMODEL];
__device__ __half g_wrqt[LATD*DMODEL];
__device__ __half g_wrkt[LATD*DMODEL];
__device__ __half g_wrvt[LATD*DMODEL];
__device__ __half g_wrot[DMODEL*LATD];
__device__ __half g_wot[DMODEL*DMODEL];

/* ================= PTX helpers (sm_80-class) ================= */

__device__ __forceinline__ uint32_t smem_to_u32(const void* p) {
    uint32_t a;
    asm("{ .reg .u64 t; cvta.to.shared.u64 t, %1; cvt.u32.u64 %0, t; }" : "=r"(a) : "l"(p));
    return a;
}

__device__ __forceinline__ void cp_async16(uint32_t dst, const void* src) {
    asm volatile("cp.async.cg.shared.global [%0], [%1], 16;" :: "r"(dst), "l"(src) : "memory");
}
#define CP_COMMIT() asm volatile("cp.async.commit_group;" ::: "memory")

__device__ __forceinline__ void ldm_x4(uint32_t r[4], uint32_t addr) {
    asm volatile("ldmatrix.sync.aligned.m8n8.x4.shared.b16 {%0,%1,%2,%3}, [%4];"
        : "=r"(r[0]), "=r"(r[1]), "=r"(r[2]), "=r"(r[3]) : "r"(addr));
}

__device__ __forceinline__ void ldm_x4_trans(uint32_t r[4], uint32_t addr) {
    asm volatile("ldmatrix.sync.aligned.m8n8.x4.trans.shared.b16 {%0,%1,%2,%3}, [%4];"
        : "=r"(r[0]), "=r"(r[1]), "=r"(r[2]), "=r"(r[3]) : "r"(addr));
}

__device__ __forceinline__ void mma_f16(float c[4], const uint32_t a[4], uint32_t b0, uint32_t b1) {
    asm volatile(
        "mma.sync.aligned.m16n8k16.row.col.f32.f16.f16.f32 "
        "{%0,%1,%2,%3}, {%4,%5,%6,%7}, {%8,%9}, {%0,%1,%2,%3};"
        : "+f"(c[0]), "+f"(c[1]), "+f"(c[2]), "+f"(c[3])
        : "r"(a[0]), "r"(a[1]), "r"(a[2]), "r"(a[3]), "r"(b0), "r"(b1));
}

__device__ __forceinline__ uint32_t packh(float x, float y) {
    __half2 t = __floats2half2_rn(x, y);
    return *reinterpret_cast<uint32_t*>(&t);
}

/* ================= conversion kernels ================= */

__global__ void fcvt_kernel(const float* __restrict__ in, __half* __restrict__ o, int n4) {
    int i = blockIdx.x * 256 + threadIdx.x;
    if (i >= n4) return;
    float4 v = reinterpret_cast<const float4*>(in)[i];
    __half2* O = reinterpret_cast<__half2*>(o);
    O[2*i]   = __floats2half2_rn(v.x, v.y);
    O[2*i+1] = __floats2half2_rn(v.z, v.w);
}

/* W[K,N] fp32 -> Wt [N,K] fp16 (transpose + convert) */
__global__ void wcvt_kernel(const float* __restrict__ W, __half* __restrict__ t16,
                            int K, int N) {
    __shared__ float t[32][33];
    int n0 = blockIdx.x * 32, k0 = blockIdx.y * 32;
    for (int r = threadIdx.y; r < 32; r += 8)
        t[r][threadIdx.x] = W[(size_t)(k0 + r) * N + n0 + threadIdx.x];
    __syncthreads();
    for (int r = threadIdx.y; r < 32; r += 8)
        t16[(size_t)(n0 + r) * K + k0 + threadIdx.x] = __float2half(t[threadIdx.x][r]);
}

/* ================= fp16 tensor-core GEMM (mma.sync, 2 CTAs/SM, K-chunk 64) ========
   C[M,N] = A[M,K] * Bt[N,K]^T + bias. fp32 out OR fp16 out.                        */

#define TSTRIDE 72
#define TILE_BYTES (128*TSTRIDE*2)       /* 18432 */
#define STAGE_BYTES (2*TILE_BYTES)       /* 36864: A, B */
#define GEMM_SMEM (2*STAGE_BYTES)        /* 73728 */

#define OFF_A 0
#define OFF_B (TILE_BYTES)

__global__ void __launch_bounds__(256, 2)
gemm_tc_kernel(const __half* __restrict__ A, const __half* __restrict__ B,
               const float* __restrict__ bias, float* __restrict__ C,
               __half* __restrict__ Ch,
               int K, int Ntot, int nch) {
    extern __shared__ char smem[];
    const uint32_t sbase = smem_to_u32(smem);
    const int tid = threadIdx.x;
    const int wid = tid >> 5, lane = tid & 31;
    const int wr = wid & 3, wc = wid >> 2;
    const int m0 = blockIdx.y * 128, n0 = blockIdx.x * 128;

    float acc[2][8][4];
#pragma unroll
    for (int i = 0; i < 2; i++)
#pragma unroll
        for (int j = 0; j < 8; j++)
#pragma unroll
            for (int e = 0; e < 4; e++) acc[i][j][e] = 0.f;

    const int lrow[4] = { tid >> 3, (tid + 256) >> 3, (tid + 512) >> 3, (tid + 768) >> 3 };
    const int lcol = (tid & 7) * 8;   /* halves */

    auto load_stage = [&](int s, int c) {
        uint32_t sb = sbase + s * STAGE_BYTES;
        const int kof = c * 64 + lcol;
#pragma unroll
        for (int it = 0; it < 4; it++) {
            int r = lrow[it];
            uint32_t so = (r * TSTRIDE + lcol) * 2;
            cp_async16(sb + OFF_A + so, A + (size_t)(m0 + r) * K + kof);
            cp_async16(sb + OFF_B + so, B + (size_t)(n0 + r) * K + kof);
        }
        CP_COMMIT();
    };

    load_stage(0, 0);

    const int a_row = wr * 32 + (lane & 15);
    const int a_kof = (lane >> 4) * 8;
    const int qd = lane >> 3;
    const int b_row = wc * 64 + ((qd & 2) << 2) + (lane & 7);
    const int b_kof = (qd & 1) * 8;

    for (int c = 0; c < nch; c++) {
        const int s = c & 1;
        if (c + 1 < nch) load_stage(s ^ 1, c + 1);
        if (c + 1 < nch) asm volatile("cp.async.wait_group 1;" ::: "memory");
        else             asm volatile("cp.async.wait_group 0;" ::: "memory");
        __syncthreads();

        const uint32_t sb = sbase + s * STAGE_BYTES;
#pragma unroll
        for (int ks = 0; ks < 4; ks++) {
            const int k0 = ks * 16;
            uint32_t ah[2][4];
#pragma unroll
            for (int i = 0; i < 2; i++) {
                uint32_t ao = ((a_row + i * 16) * TSTRIDE + k0 + a_kof) * 2;
                ldm_x4(ah[i], sb + OFF_A + ao);
            }
#pragma unroll
            for (int j2 = 0; j2 < 4; j2++) {
                uint32_t bo = ((b_row + j2 * 16) * TSTRIDE + k0 + b_kof) * 2;
                uint32_t bh[4];
                ldm_x4(bh, sb + OFF_B + bo);
#pragma unroll
                for (int i = 0; i < 2; i++)
#pragma unroll
                    for (int jj = 0; jj < 2; jj++)
                        mma_f16(acc[i][j2 * 2 + jj], ah[i], bh[jj * 2], bh[jj * 2 + 1]);
            }
        }
        __syncthreads();
    }

    const int erow = m0 + wr * 32 + (lane >> 2);
    const int ecol0 = n0 + wc * 64 + (lane & 3) * 2;
#pragma unroll
    for (int i = 0; i < 2; i++) {
#pragma unroll
        for (int j = 0; j < 8; j++) {
            int col = ecol0 + j * 8;
            float2 b2 = *reinterpret_cast<const float2*>(bias + col);
            float v0 = acc[i][j][0] + b2.x, v1 = acc[i][j][1] + b2.y;
            float v2 = acc[i][j][2] + b2.x, v3 = acc[i][j][3] + b2.y;
            size_t o0 = (size_t)(erow + i * 16) * Ntot + col;
            size_t o1 = (size_t)(erow + i * 16 + 8) * Ntot + col;
            if (C) {
                *reinterpret_cast<float2*>(C + o0) = make_float2(v0, v1);
                *reinterpret_cast<float2*>(C + o1) = make_float2(v2, v3);
            } else {
                *reinterpret_cast<__half2*>(Ch + o0) = __floats2half2_rn(v0, v1);
                *reinterpret_cast<__half2*>(Ch + o1) = __floats2half2_rn(v2, v3);
            }
        }
    }
}

/* ================= pooling ================= */
__global__ void pool_kernel(const float* __restrict__ x, float* __restrict__ pooled) {
    int bc = blockIdx.x;
    int b = bc / CHUNKS, c = bc % CHUNKS;
    int d = threadIdx.x;
    const float* base = x + ((size_t)b * SEQ + (size_t)c * CSIZE) * DMODEL + d;
    float s = 0.f;
    for (int t = 0; t < CSIZE; t++) s += base[(size_t)t * DMODEL];
    pooled[(size_t)bc * DMODEL + d] = s * (1.0f / CSIZE);
}

/* ================= FA2-style fp16 sliding-window attention (2 CTAs/SM) ============= */

#define ATT_STRIDE 72
#define ATT_TILE (128*ATT_STRIDE)
#define ATT_SMEM (3 * ATT_TILE * 2)   /* Q,K,V single = 55296 */

__global__ void __launch_bounds__(256, 2)
local_attn_tc_kernel(const __half* __restrict__ Q, const __half* __restrict__ K,
                     const __half* __restrict__ V, float* __restrict__ out) {
    extern __shared__ __half smm[];
    const uint32_t sbase = smem_to_u32(smm);
    const int qb = blockIdx.x, h = blockIdx.y, b = blockIdx.z;
    const int qstart = qb * 128;
    const int tid = threadIdx.x, wid = tid >> 5, lane = tid & 31;

    const uint32_t sQ = sbase;
    const uint32_t sK = sbase + ATT_TILE * 2;
    const uint32_t sV = sbase + 2 * ATT_TILE * 2;
    const size_t base_tok = (size_t)b * SEQ;

    auto load_q = [&]() {
#pragma unroll
        for (int it = 0; it < 4; it++) {
            int idx = tid + it * 256;
            int r = idx >> 3, c = (idx & 7) * 8;
            size_t go = (base_tok + qstart + r) * DMODEL + h * HDIM + c;
            cp_async16(sQ + (r * ATT_STRIDE + c) * 2, Q + go);
        }
    };
    auto load_kv = [&](int kstart) {
#pragma unroll
        for (int it = 0; it < 4; it++) {
            int idx = tid + it * 256;
            int r = idx >> 3, c = (idx & 7) * 8;
            size_t go = (base_tok + kstart + r) * DMODEL + h * HDIM + c;
            uint32_t so = (r * ATT_STRIDE + c) * 2;
            cp_async16(sK + so, K + go);
            cp_async16(sV + so, V + go);
        }
    };

    const int tfirst = (qb > 0) ? 0 : 1;
    load_q();
    load_kv(tfirst == 0 ? qstart - 128 : qstart);
    CP_COMMIT();
    asm volatile("cp.async.wait_group 0;" ::: "memory");
    __syncthreads();

    uint32_t ah[4][4];
    {
        int ar = wid * 16 + (lane & 15);
        int ac = (lane >> 4) * 8;
#pragma unroll
        for (int kc = 0; kc < 4; kc++)
            ldm_x4(ah[kc], sQ + (ar * ATT_STRIDE + kc * 16 + ac) * 2);
    }

    float m0 = -1e30f, m1 = -1e30f, l0 = 0.f, l1 = 0.f;
    float acc[8][4];
#pragma unroll
    for (int j = 0; j < 8; j++)
#pragma unroll
        for (int e = 0; e < 4; e++) acc[j][e] = 0.f;

    const int rloc = wid * 16 + (lane >> 2);
    const int qd2 = lane >> 3;
    const int brow = ((qd2 & 2) << 2) + (lane & 7);
    const int bkof = (qd2 & 1) * 8;
    const int vrow = (lane & 7) + ((lane >> 3) & 1) * 8;
    const int vcol = (lane >> 4) * 8;

    auto process_tile = [&](int t) {
        const int koff = (t == 0) ? 128 : 0;
#pragma unroll
        for (int hn = 0; hn < 2; hn++) {
            if (t == 0 ? (hn * 4 + 3 < wid) : (hn * 4 > wid)) continue;

            float sc[8][4];
#pragma unroll
            for (int j = 0; j < 8; j++)
#pragma unroll
                for (int e = 0; e < 4; e++) sc[j][e] = 0.f;

#pragma unroll
            for (int j2l = 0; j2l < 4; j2l++) {
                int j2g = hn * 4 + j2l;
                if (t == 0 ? (j2g < wid) : (j2g > wid)) continue;
#pragma unroll
                for (int kc = 0; kc < 4; kc++) {
                    uint32_t bh[4];
                    ldm_x4(bh, sK + ((j2g * 16 + brow) * ATT_STRIDE + kc * 16 + bkof) * 2);
                    mma_f16(sc[2 * j2l],     ah[kc], bh[0], bh[1]);
                    mma_f16(sc[2 * j2l + 1], ah[kc], bh[2], bh[3]);
                }
            }

#pragma unroll
            for (int j = 0; j < 8; j++) {
                int ck = hn * 64 + j * 8 + (lane & 3) * 2;
#pragma unroll
                for (int e = 0; e < 4; e++) {
                    int r = rloc + ((e >> 1) << 3);
                    int d = r - (ck + (e & 1)) + koff;
                    sc[j][e] = (d >= 0 && d < WIN) ? sc[j][e] * 0.125f : -INFINITY;
                }
            }

            float mx0 = -INFINITY, mx1 = -INFINITY;
#pragma unroll
            for (int j = 0; j < 8; j++) {
                mx0 = fmaxf(mx0, fmaxf(sc[j][0], sc[j][1]));
                mx1 = fmaxf(mx1, fmaxf(sc[j][2], sc[j][3]));
            }
            mx0 = fmaxf(mx0, __shfl_xor_sync(0xffffffffu, mx0, 1));
            mx0 = fmaxf(mx0, __shfl_xor_sync(0xffffffffu, mx0, 2));
            mx1 = fmaxf(mx1, __shfl_xor_sync(0xffffffffu, mx1, 1));
            mx1 = fmaxf(mx1, __shfl_xor_sync(0xffffffffu, mx1, 2));
            float mn0 = fmaxf(fmaxf(m0, mx0), -1e30f);
            float mn1 = fmaxf(fmaxf(m1, mx1), -1e30f);
            float s0 = __expf(m0 - mn0), s1 = __expf(m1 - mn1);
            m0 = mn0; m1 = mn1;
            float rs0 = 0.f, rs1 = 0.f;
#pragma unroll
            for (int j = 0; j < 8; j++) {
                sc[j][0] = __expf(sc[j][0] - mn0);
                sc[j][1] = __expf(sc[j][1] - mn0);
                sc[j][2] = __expf(sc[j][2] - mn1);
                sc[j][3] = __expf(sc[j][3] - mn1);
                rs0 += sc[j][0] + sc[j][1];
                rs1 += sc[j][2] + sc[j][3];
            }
            rs0 += __shfl_xor_sync(0xffffffffu, rs0, 1);
            rs0 += __shfl_xor_sync(0xffffffffu, rs0, 2);
            rs1 += __shfl_xor_sync(0xffffffffu, rs1, 1);
            rs1 += __shfl_xor_sync(0xffffffffu, rs1, 2);
            l0 = l0 * s0 + rs0;
            l1 = l1 * s1 + rs1;
#pragma unroll
            for (int j = 0; j < 8; j++) {
                acc[j][0] *= s0; acc[j][1] *= s0;
                acc[j][2] *= s1; acc[j][3] *= s1;
            }

#pragma unroll
            for (int kcl = 0; kcl < 4; kcl++) {
                int kcg = hn * 4 + kcl;
                if (t == 0 ? (kcg < wid) : (kcg > wid)) continue;
                uint32_t pa[4];
                pa[0] = packh(sc[2 * kcl][0],     sc[2 * kcl][1]);
                pa[1] = packh(sc[2 * kcl][2],     sc[2 * kcl][3]);
                pa[2] = packh(sc[2 * kcl + 1][0], sc[2 * kcl + 1][1]);
                pa[3] = packh(sc[2 * kcl + 1][2], sc[2 * kcl + 1][3]);
#pragma unroll
                for (int jn = 0; jn < 4; jn++) {
                    uint32_t vb[4];
                    ldm_x4_trans(vb, sV + ((kcg * 16 + vrow) * ATT_STRIDE + jn * 16 + vcol) * 2);
                    mma_f16(acc[2 * jn],     pa, vb[0], vb[1]);
                    mma_f16(acc[2 * jn + 1], pa, vb[2], vb[3]);
                }
            }
        }
    };

    process_tile(tfirst);
    if (tfirst == 0) {
        __syncthreads();
        load_kv(qstart);
        CP_COMMIT();
        asm volatile("cp.async.wait_group 0;" ::: "memory");
        __syncthreads();
        process_tile(1);
    }

    float i0 = 1.f / l0, i1 = 1.f / l1;
    size_t ob = (base_tok + qstart + rloc) * DMODEL + h * HDIM;
#pragma unroll
    for (int j = 0; j < 8; j++) {
        int col = j * 8 + (lane & 3) * 2;
        *reinterpret_cast<float2*>(out + ob + col) =
            make_float2(acc[j][0] * i0, acc[j][1] * i0);
        *reinterpret_cast<float2*>(out + ob + (size_t)8 * DMODEL + col) =
            make_float2(acc[j][2] * i1, acc[j][3] * i1);
    }
}

/* ================= latent attention (score-cached, fp16 epilogue) ================= */
#define LATENT_SMEM ((2*CHUNKS*LHDIM + 128*65) * (int)sizeof(float))

__global__ void __launch_bounds__(128, 1)
latent_attn_kernel(const float* __restrict__ rq,
                   const float* __restrict__ gk,
                   const float* __restrict__ gv,
                   __half* __restrict__ lat16) {
    extern __shared__ float sm[];
    float* Ks = sm;
    float* Vs = sm + CHUNKS * LHDIM;
    float* Sc = sm + 2 * CHUNKS * LHDIM;
    const int cid = blockIdx.x;
    const int lh = blockIdx.y, b = blockIdx.z;
    const int tid = threadIdx.x;

    const int pos = cid * 128 + tid;
    const size_t qoff = ((size_t)b * SEQ + pos) * LATD + lh * LHDIM;
    if (cid == 0) {
        __half z = __float2half(0.f);
#pragma unroll
        for (int d = 0; d < 64; d++) lat16[qoff + d] = z;
        return;
    }
    for (int idx = tid; idx < CHUNKS * LHDIM; idx += 128) {
        int c = idx >> 6, d = idx & 63;
        size_t off = ((size_t)b * CHUNKS + c) * LATD + lh * LHDIM + d;
        Ks[idx] = gk[off];
        Vs[idx] = gv[off];
    }
    __syncthreads();

    float qr[64];
#pragma unroll
    for (int d = 0; d < 64; d++) qr[d] = rq[qoff + d] * 0.125f;

    float* myS = Sc + tid * 65;
    float m = -1e30f;
    for (int c = 0; c < cid; c++) {
        const float* kr = Ks + c * 64;
        float s = 0.f;
#pragma unroll
        for (int d = 0; d < 64; d++) s += qr[d] * kr[d];
        myS[c] = s;
        m = fmaxf(m, s);
    }
    float l = 0.f;
    float acc[64];
#pragma unroll
    for (int d = 0; d < 64; d++) acc[d] = 0.f;
    for (int c = 0; c < cid; c++) {
        float p = __expf(myS[c] - m);
        l += p;
        const float* vr = Vs + c * 64;
#pragma unroll
        for (int d = 0; d < 64; d++) acc[d] += p * vr[d];
    }
    float inv = 1.f / l;
#pragma unroll
    for (int d = 0; d < 64; d++)
        lat16[qoff + d] = __float2half(acc[d] * inv);
}

/* ================= gate fuse (writes fp16 directly) ================= */
__global__ void gate_fuse_kernel(const float* __restrict__ x,
                                 const float* __restrict__ loc,
                                 const float* __restrict__ rem,
                                 const float* __restrict__ Wg,
                                 const float* __restrict__ bg,
                                 __half* __restrict__ fus16) {
    const int tkn = blockIdx.x;
    const int tid = threadIdx.x;
    __shared__ float red[128];
    const float* xr = x + (size_t)tkn * DMODEL;
    const float* lr = loc + (size_t)tkn * DMODEL;
    const float* rr = rem + (size_t)tkn * DMODEL;
    float s = 0.f;
    for (int d = tid; d < DMODEL; d += 128) s += xr[d] * Wg[d] + lr[d] * Wg[DMODEL + d];
    red[tid] = s;
    __syncthreads();
    for (int off = 64; off > 0; off >>= 1) {
        if (tid < off) red[tid] += red[tid + off];
        __syncthreads();
    }
    float g = 1.f / (1.f + __expf(-(red[0] + bg[0])));
    for (int d = tid; d < DMODEL; d += 128)
        fus16[(size_t)tkn * DMODEL + d] = __float2half(g * lr[d] + (1.f - g) * rr[d]);
}

/* ================= host ================= */

extern "C" void kernel_launch(void* const* d_in, const int* in_sizes, int n_in,
                              void* d_out, int out_size) {
    const float* x   = (const float*)d_in[0];
    const float* Wq  = (const float*)d_in[1];  const float* bq  = (const float*)d_in[2];
    const float* Wk  = (const float*)d_in[3];  const float* bk  = (const float*)d_in[4];
    const float* Wv  = (const float*)d_in[5];  const float* bv  = (const float*)d_in[6];
    const float* Wrq = (const float*)d_in[7];  const float* brq = (const float*)d_in[8];
    const float* Wrk = (const float*)d_in[9];  const float* brk = (const float*)d_in[10];
    const float* Wrv = (const float*)d_in[11]; const float* brv = (const float*)d_in[12];
    const float* Wro = (const float*)d_in[13]; const float* bro = (const float*)d_in[14];
    const float* Wo  = (const float*)d_in[15]; const float* bo  = (const float*)d_in[16];
    const float* Wg  = (const float*)d_in[17]; const float* bg  = (const float*)d_in[18];
    float* out = (float*)d_out;

    float *rq, *pooled, *gk, *gv, *loc, *rem;
    cudaGetSymbolAddress((void**)&rq, g_rq);
    cudaGetSymbolAddress((void**)&pooled, g_pooled);
    cudaGetSymbolAddress((void**)&gk, g_gk);
    cudaGetSymbolAddress((void**)&gv, g_gv);
    cudaGetSymbolAddress((void**)&loc, g_local);
    cudaGetSymbolAddress((void**)&rem, g_remote);

    __half *q16,*k16,*v16,*x16,*p16,*lat16,*fus16;
    cudaGetSymbolAddress((void**)&q16, g_q16);
    cudaGetSymbolAddress((void**)&k16, g_k16);
    cudaGetSymbolAddress((void**)&v16, g_v16);
    cudaGetSymbolAddress((void**)&x16, g_x16);
    cudaGetSymbolAddress((void**)&p16, g_p16);
    cudaGetSymbolAddress((void**)&lat16, g_lat16);
    cudaGetSymbolAddress((void**)&fus16, g_fus16);

    __half *wqt,*wkt,*wvt,*wrqt,*wrkt,*wrvt,*wrot,*wot;
    cudaGetSymbolAddress((void**)&wqt, g_wqt);
    cudaGetSymbolAddress((void**)&wkt, g_wkt);
    cudaGetSymbolAddress((void**)&wvt, g_wvt);
    cudaGetSymbolAddress((void**)&wrqt, g_wrqt);
    cudaGetSymbolAddress((void**)&wrkt, g_wrkt);
    cudaGetSymbolAddress((void**)&wrvt, g_wrvt);
    cudaGetSymbolAddress((void**)&wrot, g_wrot);
    cudaGetSymbolAddress((void**)&wot, g_wot);

    cudaFuncSetAttribute(gemm_tc_kernel,       cudaFuncAttributeMaxDynamicSharedMemorySize, GEMM_SMEM);
    cudaFuncSetAttribute(local_attn_tc_kernel, cudaFuncAttributeMaxDynamicSharedMemorySize, ATT_SMEM);
    cudaFuncSetAttribute(latent_attn_kernel,   cudaFuncAttributeMaxDynamicSharedMemorySize, LATENT_SMEM);

    /* two-stream fork/join (R11 layout: q/k/v on s0, latent chain on s2) */
    static cudaStream_t s2 = nullptr;
    static cudaEvent_t evStart, evX, evWq, evWk, evWv, evRem;
    if (!s2) {
        cudaStreamCreateWithFlags(&s2, cudaStreamNonBlocking);
        cudaEventCreateWithFlags(&evStart, cudaEventDisableTiming);
        cudaEventCreateWithFlags(&evX,   cudaEventDisableTiming);
        cudaEventCreateWithFlags(&evWq,  cudaEventDisableTiming);
        cudaEventCreateWithFlags(&evWk,  cudaEventDisableTiming);
        cudaEventCreateWithFlags(&evWv,  cudaEventDisableTiming);
        cudaEventCreateWithFlags(&evRem, cudaEventDisableTiming);
    }
    cudaStream_t s0 = 0;

    cudaEventRecord(evStart, s0);
    cudaStreamWaitEvent(s2, evStart, 0);

    /* k0: x convert (s0) */
    fcvt_kernel<<<MTOK*DMODEL/4/256, 256, 0, s0>>>(x, x16, MTOK*DMODEL/4);
    cudaEventRecord(evX, s0);

    /* Wq, Wk converts (s2) */
    wcvt_kernel<<<dim3(DMODEL/32, DMODEL/32), dim3(32,8), 0, s2>>>(Wq, wqt, DMODEL, DMODEL);
    cudaEventRecord(evWq, s2);
    wcvt_kernel<<<dim3(DMODEL/32, DMODEL/32), dim3(32,8), 0, s2>>>(Wk, wkt, DMODEL, DMODEL);
    cudaEventRecord(evWk, s2);

    /* k3: q GEMM (s0) — profiled slot */
    cudaStreamWaitEvent(s0, evWq, 0);
    gemm_tc_kernel<<<dim3(4, 256), 256, GEMM_SMEM, s0>>>(x16, wqt, bq, nullptr, q16, DMODEL, DMODEL, 8);

    wcvt_kernel<<<dim3(DMODEL/32, DMODEL/32), dim3(32,8), 0, s2>>>(Wv, wvt, DMODEL, DMODEL);
    cudaEventRecord(evWv, s2);

    cudaStreamWaitEvent(s0, evWk, 0);
    gemm_tc_kernel<<<dim3(4, 256), 256, GEMM_SMEM, s0>>>(x16, wkt, bk, nullptr, k16, DMODEL, DMODEL, 8);
    cudaStreamWaitEvent(s0, evWv, 0);
    gemm_tc_kernel<<<dim3(4, 256), 256, GEMM_SMEM, s0>>>(x16, wvt, bv, nullptr, v16, DMODEL, DMODEL, 8);

    /* rq projection on s2 (only feeds the latent chain) */
    wcvt_kernel<<<dim3(LATD/32, DMODEL/32), dim3(32,8), 0, s2>>>(Wrq, wrqt, DMODEL, LATD);
    cudaStreamWaitEvent(s2, evX, 0);
    gemm_tc_kernel<<<dim3(2, 256), 256, GEMM_SMEM, s2>>>(x16, wrqt, brq, rq, nullptr, DMODEL, LATD, 8);

    /* remaining weight prep + latent chain (s2) */
    wcvt_kernel<<<dim3(LATD/32, DMODEL/32), dim3(32,8), 0, s2>>>(Wrk, wrkt, DMODEL, LATD);
    wcvt_kernel<<<dim3(LATD/32, DMODEL/32), dim3(32,8), 0, s2>>>(Wrv, wrvt, DMODEL, LATD);
    wcvt_kernel<<<dim3(DMODEL/32, LATD/32), dim3(32,8), 0, s2>>>(Wro, wrot, LATD, DMODEL);
    wcvt_kernel<<<dim3(DMODEL/32, DMODEL/32), dim3(32,8), 0, s2>>>(Wo, wot, DMODEL, DMODEL);
    pool_kernel<<<BATCH*CHUNKS, DMODEL, 0, s2>>>(x, pooled);
    fcvt_kernel<<<BATCH*CHUNKS*DMODEL/4/256, 256, 0, s2>>>(pooled, p16, BATCH*CHUNKS*DMODEL/4);
    gemm_tc_kernel<<<dim3(2, 2), 256, GEMM_SMEM, s2>>>(p16, wrkt, brk, gk, nullptr, DMODEL, LATD, 8);
    gemm_tc_kernel<<<dim3(2, 2), 256, GEMM_SMEM, s2>>>(p16, wrvt, brv, gv, nullptr, DMODEL, LATD, 8);
    latent_attn_kernel<<<dim3(SEQ/128, LHEADS, BATCH), 128, LATENT_SMEM, s2>>>(rq, gk, gv, lat16);
    gemm_tc_kernel<<<dim3(4, 256), 256, GEMM_SMEM, s2>>>(lat16, wrot, bro, rem, nullptr, LATD, DMODEL, 4);
    cudaEventRecord(evRem, s2);

    /* local attention (s0) */
    local_attn_tc_kernel<<<dim3(SEQ/128, NHEADS, BATCH), 256, ATT_SMEM, s0>>>(q16, k16, v16, loc);

    /* join: gate + final projection (s0) */
    cudaStreamWaitEvent(s0, evRem, 0);
    gate_fuse_kernel<<<MTOK, 128, 0, s0>>>(x, loc, rem, Wg, bg, fus16);
    gemm_tc_kernel<<<dim3(4, 256), 256, GEMM_SMEM, s0>>>(fus16, wot, bo, out, nullptr, DMODEL, DMODEL, 8);
}